// round 16
// baseline (speedup 1.0000x reference)
#include <cuda_runtime.h>
#include <cuda_bf16.h>

#define FULL 0xffffffffu

namespace {
constexpr int NB   = 32;
constexpr int NP   = 32;
constexpr int DD   = 12;
constexpr int PP   = 32;
constexpr int LL   = 1024;
constexpr int LOUT = 32;
constexpr int CPL  = 4;            // cols per lane
constexpr int CP2  = CPL / 2;      // packed f32x2 pairs per lane
constexpr int WBLK = 32 * CPL;     // 128 cols per warp
constexpr int NBLK = LL / WBLK;    // 8 warps per (b,n)
constexpr float BIGV = 1e30f;
}

typedef unsigned long long u64;

// Blackwell packed fp32x2 ops (FFMA2/FADD2 in SASS — only reachable via PTX).
__device__ __forceinline__ u64 pack2(float lo, float hi) {
    u64 r; asm("mov.b64 %0, {%1, %2};" : "=l"(r) : "f"(lo), "f"(hi)); return r;
}
__device__ __forceinline__ void unpack2(u64 v, float& lo, float& hi) {
    asm("mov.b64 {%0, %1}, %2;" : "=f"(lo), "=f"(hi) : "l"(v));
}
__device__ __forceinline__ u64 ffma2(u64 a, u64 b, u64 c) {
    u64 d; asm("fma.rn.f32x2 %0, %1, %2, %3;" : "=l"(d) : "l"(a), "l"(b), "l"(c)); return d;
}
__device__ __forceinline__ u64 fadd2(u64 a, u64 b) {
    u64 d; asm("add.rn.f32x2 %0, %1, %2;" : "=l"(d) : "l"(a), "l"(b)); return d;
}
// Both-blocking named barrier over 64 threads (2 adjacent warps) — the
// deadlock-free pairwise pattern proven in R14. All participants block.
__device__ __forceinline__ void bar_pair(int id) {
    asm volatile("bar.sync %0, 64;" :: "r"(id) : "memory");
}

// One CTA (8 warps, 256 thr) per (b, n); warp w owns column block w (128
// cols). 2 CTAs/SM (128-reg cap) -> 16 warps/SM = 4 per SMSP — the axis all
// previous 12-warp variants were missing. Pairwise producer/consumer pipeline
// over 2-row steps with named barriers id=w (warps w-1 and w, both blocking):
// linear chain, consistent order => deadlock-free; adjacent skew is one step.
//
// Row recurrence (w == 1 exactly, RHO = 1.0):
//   cur[j] = c[j] + min(m[j], cur[j-1]),  m[j] = min(D[i-1,j-1], D[i-1,j])
// as composition of affine-min maps f(v) = min(beta, v + alpha) with
// (f2 o f1) = (alpha1+alpha2, min(beta2, beta1+alpha2)): one composite
// Kogge-Stone scan (5 hops). Cost rows: packed f32x2 FMAs, pattern factors
// broadcast via shfl from per-lane registers (fastest known variant, R8).
__global__ void __launch_bounds__(256, 2)
dtw_fused_kernel(const float* __restrict__ x,
                 const float* __restrict__ patts,
                 float* __restrict__ out)
{
    const int gid  = blockIdx.x;        // 0..1023
    const int b    = gid >> 5;
    const int n    = gid & 31;
    const int w    = threadIdx.x >> 5;  // column block 0..7
    const int lane = threadIdx.x & 31;

    __shared__ float carry[NBLK - 1][PP];   // carry[w][i] = D[i][(w+1)*WBLK-1]
    // carry reads are gated by the pairwise barrier protocol; no init needed.

    // lane holds patts[n][d][lane]; store -2*p for the FMA form of sqdist.
    float prow[DD];
    float p2 = 0.0f;
    {
        const float* pp = patts + n * (DD * PP) + lane;
        #pragma unroll
        for (int d = 0; d < DD; ++d) {
            float v = pp[d * PP];
            p2 = fmaf(v, v, p2);
            prow[d] = -2.0f * v;
        }
    }

    // x chunk for this warp's column block (registers, packed f32x2).
    const float* xb = x + b * (DD * LL);
    const int j0 = w * WBLK;
    u64 xp[DD][CP2];
    u64 px2[CP2];
    {
        u64 z = pack2(0.0f, 0.0f);
        #pragma unroll
        for (int k2 = 0; k2 < CP2; ++k2) px2[k2] = z;
    }
    #pragma unroll
    for (int d = 0; d < DD; ++d) {
        float4 v0 = *reinterpret_cast<const float4*>(xb + d * LL + j0 + CPL * lane);
        xp[d][0] = pack2(v0.x, v0.y);
        xp[d][1] = pack2(v0.z, v0.w);
        #pragma unroll
        for (int k2 = 0; k2 < CP2; ++k2)
            px2[k2] = ffma2(xp[d][k2], xp[d][k2], px2[k2]);
    }

    float* outb = out + ((b * NP + n) * PP) * LOUT;
    float Dp[CPL];   // previous DP row for this warp's block

    // One full row update; on return Dp[k] == cur[k].
    auto rowcalc = [&](int i, float bl, float bm) {
        // cost row (alpha): packed FMAs; pattern factors broadcast via shfl
        float p2b = __shfl_sync(FULL, p2, i);
        u64 p2b2 = pack2(p2b, p2b);
        u64 cc[CP2];
        #pragma unroll
        for (int k2 = 0; k2 < CP2; ++k2) cc[k2] = fadd2(p2b2, px2[k2]);
        #pragma unroll
        for (int d = 0; d < DD; ++d) {
            float pb = __shfl_sync(FULL, prow[d], i);
            u64 pbb = pack2(pb, pb);
            #pragma unroll
            for (int k2 = 0; k2 < CP2; ++k2)
                cc[k2] = ffma2(pbb, xp[d][k2], cc[k2]);
        }
        float c[CPL];
        #pragma unroll
        for (int k2 = 0; k2 < CP2; ++k2)
            unpack2(cc[k2], c[2 * k2], c[2 * k2 + 1]);

        // local inclusive composites (A = prefix sum of c, B = bound)
        float A[CPL], Bv[CPL];
        float shin = __shfl_up_sync(FULL, Dp[CPL - 1], 1);
        if (i == 0) {
            A[0] = c[0]; Bv[0] = BIGV;
            #pragma unroll
            for (int k = 1; k < CPL; ++k) { A[k] = A[k - 1] + c[k]; Bv[k] = BIGV; }
        } else {
            float m0 = fminf((lane == 0) ? bm : shin, Dp[0]);
            A[0]  = c[0];
            Bv[0] = c[0] + m0;
            #pragma unroll
            for (int k = 1; k < CPL; ++k) {
                float mk = fminf(Dp[k - 1], Dp[k]);
                A[k]  = A[k - 1] + c[k];
                Bv[k] = fminf(c[k] + mk, Bv[k - 1] + c[k]);
            }
        }

        // single composite warp scan over lane maps (5 hops)
        float Aw = A[CPL - 1], Bw = Bv[CPL - 1];
        #pragma unroll
        for (int o = 1; o < 32; o <<= 1) {
            float Au = __shfl_up_sync(FULL, Aw, o);
            float Bu = __shfl_up_sync(FULL, Bw, o);
            if (lane >= o) {
                Bw = fminf(Bw, Bu + Aw);  // uses pre-update Aw
                Aw = Aw + Au;
            }
        }
        float Ae = __shfl_up_sync(FULL, Aw, 1);
        float Be = __shfl_up_sync(FULL, Bw, 1);
        float vin = (lane == 0) ? bl : fminf(Be, bl + Ae);

        #pragma unroll
        for (int k = 0; k < CPL; ++k)
            Dp[k] = fminf(Bv[k], vin + A[k]);   // cur -> becomes prev row

        // output tail: cols 992..1023 = lanes 24..31 of the last warp
        if (w == NBLK - 1 && lane >= 24) {
            float* po = outb + i * LOUT + (lane - 24) * CPL;
            *reinterpret_cast<float4*>(po) = make_float4(Dp[0], Dp[1], Dp[2], Dp[3]);
        }
    };

    float bmr = BIGV;   // carry[w-1][i0-1], held in a register across steps

    #pragma unroll 1
    for (int i0 = 0; i0 < PP; i0 += 2) {
        float bl0, bm0, bl1, bm1;
        if (w == 0) {
            bl0 = (i0 == 0) ? 0.0f : BIGV;   // D[0,0] seed enters as v
            bm0 = BIGV;                       // D[i-1][-1] always OOR at w==0
            bl1 = BIGV;
            bm1 = BIGV;
        } else {
            bar_pair(w);                      // rows 0..i0+1 of warp w-1 published
            bl0 = carry[w - 1][i0];
            bm0 = bmr;                        // = carry[w-1][i0-1]
            bl1 = carry[w - 1][i0 + 1];
            bm1 = bl0;                        // = carry[w-1][i0]
        }

        rowcalc(i0, bl0, bm0);
        if (w < NBLK - 1 && lane == 31) carry[w][i0] = Dp[CPL - 1];

        rowcalc(i0 + 1, bl1, bm1);
        if (w < NBLK - 1 && lane == 31) carry[w][i0 + 1] = Dp[CPL - 1];

        if (w < NBLK - 1) bar_pair(w + 1);    // hand both rows to warp w+1
        bmr = bl1;
    }
}

extern "C" void kernel_launch(void* const* d_in, const int* in_sizes, int n_in,
                              void* d_out, int out_size) {
    const float* x     = (const float*)d_in[0];   // [32, 12, 1024]
    const float* patts = (const float*)d_in[1];   // [32, 12, 32]
    float* out = (float*)d_out;                   // [32, 32, 32, 32]
    (void)in_sizes; (void)n_in; (void)out_size;
    dtw_fused_kernel<<<NB * NP, 256>>>(x, patts, out);
}

// round 17
// speedup vs baseline: 1.2911x; 1.2911x over previous
#include <cuda_runtime.h>
#include <cuda_bf16.h>

#define FULL 0xffffffffu

namespace {
constexpr int NB   = 32;
constexpr int NP   = 32;
constexpr int DD   = 12;
constexpr int PP   = 32;
constexpr int LL   = 1024;
constexpr int LOUT = 32;
constexpr int CPL  = 8;            // cols per lane
constexpr int CP2  = CPL / 2;      // packed f32x2 pairs per lane
constexpr int WBLK = 32 * CPL;     // 256 cols per warp
constexpr int NBLK = LL / WBLK;    // 4 warps per (b,n)
constexpr float BIGV = 1e30f;
}

typedef unsigned long long u64;

// Blackwell packed fp32x2 ops (FFMA2/FADD2 in SASS — only reachable via PTX).
__device__ __forceinline__ u64 pack2(float lo, float hi) {
    u64 r; asm("mov.b64 %0, {%1, %2};" : "=l"(r) : "f"(lo), "f"(hi)); return r;
}
__device__ __forceinline__ void unpack2(u64 v, float& lo, float& hi) {
    asm("mov.b64 {%0, %1}, %2;" : "=f"(lo), "=f"(hi) : "l"(v));
}
__device__ __forceinline__ u64 ffma2(u64 a, u64 b, u64 c) {
    u64 d; asm("fma.rn.f32x2 %0, %1, %2, %3;" : "=l"(d) : "l"(a), "l"(b), "l"(c)); return d;
}
__device__ __forceinline__ u64 fadd2(u64 a, u64 b) {
    u64 d; asm("add.rn.f32x2 %0, %1, %2;" : "=l"(d) : "l"(a), "l"(b)); return d;
}

// One CTA (4 warps) per (b, n); warp w owns column block w (256 cols).
// Diagonal wavefront with TWO rows per step: at step t, warp w computes rows
// 2(t-w) and 2(t-w)+1; one __syncthreads per step (19 barriers, not 35).
// Warp w-1 published rows 2(t-w), 2(t-w)+1 at its previous step, so all
// carries are barrier-ordered. Inside a step, row i0+1's cost FMAs are
// independent of row i0's scan chain — ptxas interleaves them into the
// scan-hop stalls (the R2 overlap, finally applied to the R8 structure).
//
// Row recurrence (w == 1 exactly, RHO = 1.0):
//   cur[j] = c[j] + min(m[j], cur[j-1]),  m[j] = min(D[i-1,j-1], D[i-1,j])
// as composition of affine-min maps f(v) = min(beta, v + alpha) with
// (f2 o f1) = (alpha1+alpha2, min(beta2, beta1+alpha2)): one composite
// Kogge-Stone scan (5 hops). Cost rows: packed f32x2 FMAs, pattern factors
// broadcast via shfl from per-lane registers (R8, fastest known variant).
__global__ void __launch_bounds__(128, 3)
dtw_fused_kernel(const float* __restrict__ x,
                 const float* __restrict__ patts,
                 float* __restrict__ out)
{
    const int gid  = blockIdx.x;        // 0..1023
    const int b    = gid >> 5;
    const int n    = gid & 31;
    const int w    = threadIdx.x >> 5;  // column block 0..3
    const int lane = threadIdx.x & 31;

    __shared__ float carry[NBLK - 1][PP];   // carry[w][i] = D[i][(w+1)*WBLK - 1]

    // lane holds patts[n][d][lane]; store -2*p for the FMA form of sqdist.
    float prow[DD];
    float p2 = 0.0f;
    {
        const float* pp = patts + n * (DD * PP) + lane;
        #pragma unroll
        for (int d = 0; d < DD; ++d) {
            float v = pp[d * PP];
            p2 = fmaf(v, v, p2);
            prow[d] = -2.0f * v;
        }
    }

    // x chunk for this warp's column block (registers, packed f32x2).
    const float* xb = x + b * (DD * LL);
    const int j0 = w * WBLK;
    u64 xp[DD][CP2];
    u64 px2[CP2];
    {
        u64 z = pack2(0.0f, 0.0f);
        #pragma unroll
        for (int k2 = 0; k2 < CP2; ++k2) px2[k2] = z;
    }
    #pragma unroll
    for (int d = 0; d < DD; ++d) {
        const float* px = xb + d * LL + j0 + CPL * lane;
        float4 v0 = *reinterpret_cast<const float4*>(px);
        float4 v1 = *reinterpret_cast<const float4*>(px + 4);
        xp[d][0] = pack2(v0.x, v0.y);
        xp[d][1] = pack2(v0.z, v0.w);
        xp[d][2] = pack2(v1.x, v1.y);
        xp[d][3] = pack2(v1.z, v1.w);
        #pragma unroll
        for (int k2 = 0; k2 < CP2; ++k2)
            px2[k2] = ffma2(xp[d][k2], xp[d][k2], px2[k2]);
    }

    float* outb = out + ((b * NP + n) * PP) * LOUT;
    float Dp[CPL];   // previous DP row for this warp's block

    // One full row update; on return Dp[k] == cur[k].
    auto rowcalc = [&](int i, float bl, float bm) {
        // ---- cost row c[k] (alpha), packed f32x2 ----
        float p2b = __shfl_sync(FULL, p2, i);
        u64 p2b2 = pack2(p2b, p2b);
        u64 cc[CP2];
        #pragma unroll
        for (int k2 = 0; k2 < CP2; ++k2) cc[k2] = fadd2(p2b2, px2[k2]);
        #pragma unroll
        for (int d = 0; d < DD; ++d) {
            float pb = __shfl_sync(FULL, prow[d], i);
            u64 pbb = pack2(pb, pb);
            #pragma unroll
            for (int k2 = 0; k2 < CP2; ++k2)
                cc[k2] = ffma2(pbb, xp[d][k2], cc[k2]);
        }
        float c[CPL];
        #pragma unroll
        for (int k2 = 0; k2 < CP2; ++k2)
            unpack2(cc[k2], c[2 * k2], c[2 * k2 + 1]);

        // ---- local inclusive composites (A = prefix sum of c, B = bound) ----
        float A[CPL], Bv[CPL];
        float shin = __shfl_up_sync(FULL, Dp[CPL - 1], 1);
        if (i == 0) {
            A[0] = c[0]; Bv[0] = BIGV;
            #pragma unroll
            for (int k = 1; k < CPL; ++k) { A[k] = A[k - 1] + c[k]; Bv[k] = BIGV; }
        } else {
            float m0 = fminf((lane == 0) ? bm : shin, Dp[0]);
            A[0]  = c[0];
            Bv[0] = c[0] + m0;
            #pragma unroll
            for (int k = 1; k < CPL; ++k) {
                float mk = fminf(Dp[k - 1], Dp[k]);
                A[k]  = A[k - 1] + c[k];
                Bv[k] = fminf(c[k] + mk, Bv[k - 1] + c[k]);
            }
        }

        // ---- single composite warp scan over lane maps (5 hops) ----
        float Aw = A[CPL - 1], Bw = Bv[CPL - 1];
        #pragma unroll
        for (int o = 1; o < 32; o <<= 1) {
            float Au = __shfl_up_sync(FULL, Aw, o);
            float Bu = __shfl_up_sync(FULL, Bw, o);
            if (lane >= o) {
                Bw = fminf(Bw, Bu + Aw);  // uses pre-update Aw
                Aw = Aw + Au;
            }
        }
        float Ae = __shfl_up_sync(FULL, Aw, 1);
        float Be = __shfl_up_sync(FULL, Bw, 1);
        float vin = (lane == 0) ? bl : fminf(Be, bl + Ae);

        // ---- cur[k] = min(B[k], vin + A[k]) -> becomes prev row ----
        #pragma unroll
        for (int k = 0; k < CPL; ++k)
            Dp[k] = fminf(Bv[k], vin + A[k]);

        // ---- publish carry for the warp to the right ----
        if (w < NBLK - 1 && lane == 31) carry[w][i] = Dp[CPL - 1];

        // ---- output tail: cols 992..1023 = lanes 28..31 of last warp ----
        if (w == NBLK - 1 && lane >= 28) {
            float* po = outb + i * LOUT + (lane - 28) * CPL;
            *reinterpret_cast<float4*>(po)     = make_float4(Dp[0], Dp[1], Dp[2], Dp[3]);
            *reinterpret_cast<float4*>(po + 4) = make_float4(Dp[4], Dp[5], Dp[6], Dp[7]);
        }
    };

    #pragma unroll 1
    for (int t = 0; t < PP / 2 + NBLK - 1; ++t) {
        const int i0 = 2 * (t - w);
        if (i0 >= 0 && i0 < PP) {
            // boundary carries for rows i0 and i0+1 (barrier-ordered smem)
            float bl0, bm0, bl1, bm1;
            if (w == 0) {
                bl0 = (i0 == 0) ? 0.0f : BIGV;   // D[0,0] seed enters as v
                bm0 = BIGV;                       // D[i-1][-1] always OOR
                bl1 = BIGV;
                bm1 = BIGV;
            } else {
                bl0 = carry[w - 1][i0];
                bm0 = (i0 > 0) ? carry[w - 1][i0 - 1] : BIGV;
                bl1 = carry[w - 1][i0 + 1];
                bm1 = bl0;                        // = carry[w-1][i0]
            }

            rowcalc(i0, bl0, bm0);
            rowcalc(i0 + 1, bl1, bm1);
        }
        __syncthreads();
    }
}

extern "C" void kernel_launch(void* const* d_in, const int* in_sizes, int n_in,
                              void* d_out, int out_size) {
    const float* x     = (const float*)d_in[0];   // [32, 12, 1024]
    const float* patts = (const float*)d_in[1];   // [32, 12, 32]
    float* out = (float*)d_out;                   // [32, 32, 32, 32]
    (void)in_sizes; (void)n_in; (void)out_size;
    dtw_fused_kernel<<<NB * NP, 128>>>(x, patts, out);
}